// round 11
// baseline (speedup 1.0000x reference)
#include <cuda_runtime.h>
#include <cuda_bf16.h>

#define Dm 1024
#define Tm 2048
#define Lm 4

typedef unsigned long long u64;

// ---------------- device scratch (allocation-free rule) ---------------------
__device__ __align__(16) float g_seq[2][Tm * Dm];            // ping-pong seq
__device__ __align__(16) float g_zx[(size_t)Tm * 4 * Dm];    // x-part + bias
__device__ __align__(16) u64   g_ht[2][Dm];                  // {tag<<32|h bits}, by step parity

// ---------------- f32x2 helpers (sm_103a packed fp32) -----------------------
__device__ __forceinline__ u64 ffma2(u64 a, u64 b, u64 c) {
    u64 d;
    asm("fma.rn.f32x2 %0, %1, %2, %3;" : "=l"(d) : "l"(a), "l"(b), "l"(c));
    return d;
}
__device__ __forceinline__ u64 fadd2(u64 a, u64 b) {
    u64 d;
    asm("add.rn.f32x2 %0, %1, %2;" : "=l"(d) : "l"(a), "l"(b));
    return d;
}
__device__ __forceinline__ u64 pack2(float x, float y) {
    u64 r;
    asm("mov.b64 %0, {%1, %2};" : "=l"(r)
        : "r"(__float_as_uint(x)), "r"(__float_as_uint(y)));
    return r;
}
__device__ __forceinline__ float hsum2(u64 v) {
    unsigned lo, hi;
    asm("mov.b64 {%0, %1}, %2;" : "=r"(lo), "=r"(hi) : "l"(v));
    return __uint_as_float(lo) + __uint_as_float(hi);
}
__device__ __forceinline__ u64 ld_rlx64(const u64* p) {
    u64 v;
    asm volatile("ld.relaxed.gpu.global.b64 %0, [%1];" : "=l"(v) : "l"(p) : "memory");
    return v;
}
__device__ __forceinline__ void st_rlx64(u64* p, u64 v) {
    asm volatile("st.relaxed.gpu.global.b64 [%0], %1;" :: "l"(p), "l"(v) : "memory");
}

// ---------------- kernel 1: persistent Re bias-add ---------------------------
__global__ void bias_kernel(const float* __restrict__ x, const float* __restrict__ rn,
                            const float* __restrict__ w, const float* __restrict__ b) {
    int i = blockIdx.x * 256 + threadIdx.x;
    int j = i & (Dm - 1);
    g_seq[0][i] = x[i] + rn[0] * w[j] + b[j];
}

// ---------------- kernel 2: Zx = seq_in @ Wx + bias (f32x2 GEMM) -------------
// C tile 128(m) x 64(n), BK = 16, 256 threads, 8x4 per thread.
__global__ __launch_bounds__(256, 2) void gemm_zx(
    const float* __restrict__ Wf1, const float* __restrict__ Wf2,
    const float* __restrict__ Wta, const float* __restrict__ Wtb,
    const float* __restrict__ bf1, const float* __restrict__ bf2,
    const float* __restrict__ bta, const float* __restrict__ btb,
    int layer)
{
    __shared__ u64   As2[8][128];      // [k-pair][m]
    __shared__ float Bsf[8][64][2];    // [k-pair][n][k parity]

    const int tid = threadIdx.x;
    const int tx = tid & 15;
    const int ty = tid >> 4;
    const int m0 = blockIdx.y * 128;
    const int n0 = blockIdx.x * 64;
    const int blk = n0 >> 10;
    const int j0  = n0 & (Dm - 1);

    const float* Wb = (blk == 0) ? Wf1 : ((blk == 1) ? Wf2 : ((blk == 2) ? Wta : Wtb));
    const float* bb = (blk == 0) ? bf1 : ((blk == 1) ? bf2 : ((blk == 2) ? bta : btb));
    const float* Bp = Wb + (size_t)layer * 2 * Dm * Dm + j0;
    const float* A  = g_seq[layer & 1];

    u64 acc[8][4];
#pragma unroll
    for (int i = 0; i < 8; i++)
#pragma unroll
        for (int j = 0; j < 4; j++) acc[i][j] = 0ull;

    for (int k0 = 0; k0 < Dm; k0 += 16) {
#pragma unroll
        for (int it = 0; it < 2; it++) {
            int i   = tid + it * 256;
            int row = i >> 2;
            int f4  = i & 3;
            float4 v = *(const float4*)(A + (size_t)(m0 + row) * Dm + k0 + f4 * 4);
            As2[f4 * 2 + 0][row] = pack2(v.x, v.y);
            As2[f4 * 2 + 1][row] = pack2(v.z, v.w);
        }
        {
            int kr = tid >> 4;
            int j4 = tid & 15;
            float4 v = *(const float4*)(Bp + (size_t)(k0 + kr) * Dm + j4 * 4);
            Bsf[kr >> 1][j4 * 4 + 0][kr & 1] = v.x;
            Bsf[kr >> 1][j4 * 4 + 1][kr & 1] = v.y;
            Bsf[kr >> 1][j4 * 4 + 2][kr & 1] = v.z;
            Bsf[kr >> 1][j4 * 4 + 3][kr & 1] = v.w;
        }
        __syncthreads();
#pragma unroll
        for (int kk = 0; kk < 8; kk++) {
            u64 a2[8], b2[4];
#pragma unroll
            for (int ii = 0; ii < 8; ii++) a2[ii] = As2[kk][ii * 16 + ty];
#pragma unroll
            for (int jj = 0; jj < 4; jj++) b2[jj] = *(const u64*)&Bsf[kk][jj * 16 + tx][0];
#pragma unroll
            for (int ii = 0; ii < 8; ii++)
#pragma unroll
                for (int jj = 0; jj < 4; jj++)
                    acc[ii][jj] = ffma2(a2[ii], b2[jj], acc[ii][jj]);
        }
        __syncthreads();
    }

    float bias[4];
#pragma unroll
    for (int jj = 0; jj < 4; jj++) bias[jj] = bb[(size_t)layer * Dm + j0 + jj * 16 + tx];
#pragma unroll
    for (int ii = 0; ii < 8; ii++) {
        size_t row = (size_t)(m0 + ii * 16 + ty);
#pragma unroll
        for (int jj = 0; jj < 4; jj++)
            g_zx[row * 4096 + n0 + jj * 16 + tx] = hsum2(acc[ii][jj]) + bias[jj];
    }
}

// ---------------- kernel 3: sequential scan (tagged-word sync, 2 buffers) ----
// 128 CTAs x 256 threads, persistent. CTA b owns dims 8b..8b+7, warp w -> dim.
// Lane = blk*8 + chunk: blk picks gate matrix, chunk picks 128-wide k range.
// h_t lives in g_ht[t&1] as {tag|bits}; consumers spin until tag == base+t.
// Double buffering makes the <=1-step producer skew safe (no overwrite-before-read).
__global__ __launch_bounds__(256, 1) void scan_kernel(
    const float* __restrict__ Wf1, const float* __restrict__ Wf2,
    const float* __restrict__ Wta, const float* __restrict__ Wtb,
    const float* __restrict__ dt_ptr, int layer)
{
    __shared__ __align__(16) float sh[2][Dm];   // double-buffered h stage

    const int tid  = threadIdx.x;
    const int lane = tid & 31;
    const int w    = tid >> 5;               // warp -> dim
    const int blk  = lane >> 3;              // gate 0..3
    const int ch   = lane & 7;               // k chunk
    const int dim  = blockIdx.x * 8 + w;
    const float dt = dt_ptr[0];
    const unsigned tagbase = (unsigned)layer * (unsigned)Tm;

    const float* Wsel = (blk == 0) ? Wf1 : ((blk == 1) ? Wf2 : ((blk == 2) ? Wta : Wtb));
    const float* Wp = Wsel + (size_t)layer * 2 * Dm * Dm
                    + (size_t)(Dm + ch * 128) * Dm + dim;

    // this lane's 128 Wh values as 64 f32x2 pairs
    u64 wreg[64];
#pragma unroll
    for (int i = 0; i < 64; i++)
        wreg[i] = pack2(Wp[(size_t)(2 * i) * Dm], Wp[(size_t)(2 * i + 1) * Dm]);

    float* __restrict__ outseq = g_seq[(layer + 1) & 1];
    const bool zlane = (ch == 0);
    float zx_cur = zlane ? __ldg(&g_zx[(size_t)blk * Dm + dim]) : 0.0f;

    // staging indices (fixed per thread): handles h[sc*128 + sf*4 .. +3]
    const int sc = tid & 7, sf = tid >> 3;
    const int htoff = sc * 128 + sf * 4;
    float* const mysh0 = &sh[0][sf * 32 + sc * 4];
    float* const mysh1 = &sh[1][sf * 32 + sc * 4];

    for (int t = 0; t < Tm; ++t) {
        float* mysh = (t & 1) ? mysh1 : mysh0;

        // prefetch Zx for next step early (latency hides under the poll)
        float zx_next = (zlane && t + 1 < Tm)
            ? __ldg(&g_zx[(size_t)(t + 1) * 4096 + blk * Dm + dim]) : 0.0f;

        // ---- acquire + stage h_t (tag-embedded words, parity buffer) ----
        if (t == 0) {
            mysh[0] = 0.0f; mysh[1] = 0.0f; mysh[2] = 0.0f; mysh[3] = 0.0f;
        } else {
            const u64* myht = &g_ht[t & 1][htoff];
            const unsigned target = tagbase + (unsigned)t;
            u64 r0, r1, r2, r3;
            for (;;) {
                r0 = ld_rlx64(myht + 0);
                r1 = ld_rlx64(myht + 1);
                r2 = ld_rlx64(myht + 2);
                r3 = ld_rlx64(myht + 3);
                if ((unsigned)(r0 >> 32) == target && (unsigned)(r1 >> 32) == target &&
                    (unsigned)(r2 >> 32) == target && (unsigned)(r3 >> 32) == target)
                    break;
            }
            mysh[0] = __uint_as_float((unsigned)r0);
            mysh[1] = __uint_as_float((unsigned)r1);
            mysh[2] = __uint_as_float((unsigned)r2);
            mysh[3] = __uint_as_float((unsigned)r3);
        }
        __syncthreads();

        // ---- partial dot: 128 k via 64 packed FMAs, 4 accumulator chains ----
        u64 a0 = 0ull, a1 = 0ull, a2 = 0ull, a3 = 0ull;
        const float4* sh4 = (const float4*)sh[t & 1];
#pragma unroll
        for (int f = 0; f < 32; f += 2) {
            float4 h0 = sh4[f * 8 + ch];
            float4 h1 = sh4[(f + 1) * 8 + ch];
            a0 = ffma2(pack2(h0.x, h0.y), wreg[2 * f + 0], a0);
            a1 = ffma2(pack2(h0.z, h0.w), wreg[2 * f + 1], a1);
            a2 = ffma2(pack2(h1.x, h1.y), wreg[2 * f + 2], a2);
            a3 = ffma2(pack2(h1.z, h1.w), wreg[2 * f + 3], a3);
        }
        float s = hsum2(fadd2(fadd2(a0, a1), fadd2(a2, a3)));
        s += __shfl_xor_sync(0xffffffffu, s, 1);
        s += __shfl_xor_sync(0xffffffffu, s, 2);
        s += __shfl_xor_sync(0xffffffffu, s, 4);
        if (zlane) s += zx_cur;

        float z1 = __shfl_sync(0xffffffffu, s, 0);
        float z2 = __shfl_sync(0xffffffffu, s, 8);
        float za = __shfl_sync(0xffffffffu, s, 16);
        float zb = __shfl_sync(0xffffffffu, s, 24);

        float f1 = tanhf(z1);
        float f2 = tanhf(z2);
        float g  = __fdividef(1.0f, 1.0f + expf(za * dt - zb));  // sigmoid(-za*dt+zb)
        float hn = g * f1 + (1.0f - g) * f2;

        if (lane == 0) {
            // publish h(t+1) into parity buffer (t+1)&1; tag rides with bits
            u64 pk = ((u64)(tagbase + (unsigned)(t + 1)) << 32)
                   | (u64)__float_as_uint(hn);
            st_rlx64(&g_ht[(t + 1) & 1][dim], pk);
            outseq[(size_t)t * Dm + dim] = hn;
        }
        zx_cur = zx_next;
        // no trailing sync: double-buffered sh + next-iter sync protects reuse
    }
}

// ---------------- kernel 4: emit final h -------------------------------------
__global__ void copy_out_kernel(float* __restrict__ out) {
    out[threadIdx.x] = g_seq[0][(size_t)(Tm - 1) * Dm + threadIdx.x];
}

// ---------------- launch ------------------------------------------------------
extern "C" void kernel_launch(void* const* d_in, const int* in_sizes, int n_in,
                              void* d_out, int out_size) {
    const float* x    = (const float*)d_in[0];
    const float* rn   = (const float*)d_in[1];
    const float* dtp  = (const float*)d_in[2];
    const float* rw   = (const float*)d_in[3];
    const float* rb   = (const float*)d_in[4];
    const float* Wf1  = (const float*)d_in[5];
    const float* bf1  = (const float*)d_in[6];
    const float* Wf2  = (const float*)d_in[7];
    const float* bf2  = (const float*)d_in[8];
    const float* Wta  = (const float*)d_in[9];
    const float* bta  = (const float*)d_in[10];
    const float* Wtb  = (const float*)d_in[11];
    const float* btb  = (const float*)d_in[12];

    bias_kernel<<<(Tm * Dm) / 256, 256>>>(x, rn, rw, rb);

    for (int l = 0; l < Lm; ++l) {
        dim3 grid(4 * Dm / 64, Tm / 128);
        gemm_zx<<<grid, 256>>>(Wf1, Wf2, Wta, Wtb, bf1, bf2, bta, btb, l);
        scan_kernel<<<128, 256>>>(Wf1, Wf2, Wta, Wtb, dtp, l);
    }

    copy_out_kernel<<<1, Dm>>>((float*)d_out);
}

// round 12
// speedup vs baseline: 2.0208x; 2.0208x over previous
#include <cuda_runtime.h>
#include <cuda_bf16.h>

#define Dm 1024
#define Tm 2048
#define Lm 4

typedef unsigned long long u64;

// ---------------- device scratch (allocation-free rule) ---------------------
__device__ __align__(16) float g_seq[2][Tm * Dm];            // ping-pong seq
__device__ __align__(16) float g_zx[(size_t)Tm * 4 * Dm];    // x-part + bias
__device__ __align__(16) float g_h[2][Dm];                   // h double buffer
__device__ unsigned g_bar_count;                             // monotonic / launch

// ---------------- f32x2 helpers (sm_103a packed fp32) -----------------------
__device__ __forceinline__ u64 ffma2(u64 a, u64 b, u64 c) {
    u64 d;
    asm("fma.rn.f32x2 %0, %1, %2, %3;" : "=l"(d) : "l"(a), "l"(b), "l"(c));
    return d;
}
__device__ __forceinline__ u64 fadd2(u64 a, u64 b) {
    u64 d;
    asm("add.rn.f32x2 %0, %1, %2;" : "=l"(d) : "l"(a), "l"(b));
    return d;
}
__device__ __forceinline__ u64 pack2(float x, float y) {
    u64 r;
    asm("mov.b64 %0, {%1, %2};" : "=l"(r)
        : "r"(__float_as_uint(x)), "r"(__float_as_uint(y)));
    return r;
}
__device__ __forceinline__ float hsum2(u64 v) {
    unsigned lo, hi;
    asm("mov.b64 {%0, %1}, %2;" : "=r"(lo), "=r"(hi) : "l"(v));
    return __uint_as_float(lo) + __uint_as_float(hi);
}

// fast, saturation-safe tanh / sigmoid (MUFU-based)
__device__ __forceinline__ float fast_tanh(float x) {
    float e = __expf(-2.0f * fabsf(x));           // in (0,1]
    float r = __fdividef(1.0f - e, 1.0f + e);
    return copysignf(r, x);
}
__device__ __forceinline__ float fast_sigmoid(float u) {      // sigmoid(u)
    float e = __expf(-fabsf(u));                  // in (0,1]
    float r = __fdividef(1.0f, 1.0f + e);         // correct for u>=0
    return (u >= 0.0f) ? r : (1.0f - r);
}

// ---------------- kernel 1: persistent Re bias-add + barrier reset ----------
__global__ void bias_kernel(const float* __restrict__ x, const float* __restrict__ rn,
                            const float* __restrict__ w, const float* __restrict__ b) {
    if (blockIdx.x == 0 && threadIdx.x == 0) g_bar_count = 0u;
    int i = blockIdx.x * 256 + threadIdx.x;
    int j = i & (Dm - 1);
    g_seq[0][i] = x[i] + rn[0] * w[j] + b[j];
}

// ---------------- kernel 2: Zx = seq_in @ Wx + bias (f32x2 GEMM) -------------
// C tile 128(m) x 64(n), BK = 16, 256 threads, 8x4 per thread.
__global__ __launch_bounds__(256, 2) void gemm_zx(
    const float* __restrict__ Wf1, const float* __restrict__ Wf2,
    const float* __restrict__ Wta, const float* __restrict__ Wtb,
    const float* __restrict__ bf1, const float* __restrict__ bf2,
    const float* __restrict__ bta, const float* __restrict__ btb,
    int layer)
{
    __shared__ u64   As2[8][128];      // [k-pair][m]
    __shared__ float Bsf[8][64][2];    // [k-pair][n][k parity]

    const int tid = threadIdx.x;
    const int tx = tid & 15;
    const int ty = tid >> 4;
    const int m0 = blockIdx.y * 128;
    const int n0 = blockIdx.x * 64;
    const int blk = n0 >> 10;
    const int j0  = n0 & (Dm - 1);

    const float* Wb = (blk == 0) ? Wf1 : ((blk == 1) ? Wf2 : ((blk == 2) ? Wta : Wtb));
    const float* bb = (blk == 0) ? bf1 : ((blk == 1) ? bf2 : ((blk == 2) ? bta : btb));
    const float* Bp = Wb + (size_t)layer * 2 * Dm * Dm + j0;
    const float* A  = g_seq[layer & 1];

    u64 acc[8][4];
#pragma unroll
    for (int i = 0; i < 8; i++)
#pragma unroll
        for (int j = 0; j < 4; j++) acc[i][j] = 0ull;

    for (int k0 = 0; k0 < Dm; k0 += 16) {
#pragma unroll
        for (int it = 0; it < 2; it++) {
            int i   = tid + it * 256;
            int row = i >> 2;
            int f4  = i & 3;
            float4 v = *(const float4*)(A + (size_t)(m0 + row) * Dm + k0 + f4 * 4);
            As2[f4 * 2 + 0][row] = pack2(v.x, v.y);
            As2[f4 * 2 + 1][row] = pack2(v.z, v.w);
        }
        {
            int kr = tid >> 4;
            int j4 = tid & 15;
            float4 v = *(const float4*)(Bp + (size_t)(k0 + kr) * Dm + j4 * 4);
            Bsf[kr >> 1][j4 * 4 + 0][kr & 1] = v.x;
            Bsf[kr >> 1][j4 * 4 + 1][kr & 1] = v.y;
            Bsf[kr >> 1][j4 * 4 + 2][kr & 1] = v.z;
            Bsf[kr >> 1][j4 * 4 + 3][kr & 1] = v.w;
        }
        __syncthreads();
#pragma unroll
        for (int kk = 0; kk < 8; kk++) {
            u64 a2[8], b2[4];
#pragma unroll
            for (int ii = 0; ii < 8; ii++) a2[ii] = As2[kk][ii * 16 + ty];
#pragma unroll
            for (int jj = 0; jj < 4; jj++) b2[jj] = *(const u64*)&Bsf[kk][jj * 16 + tx][0];
#pragma unroll
            for (int ii = 0; ii < 8; ii++)
#pragma unroll
                for (int jj = 0; jj < 4; jj++)
                    acc[ii][jj] = ffma2(a2[ii], b2[jj], acc[ii][jj]);
        }
        __syncthreads();
    }

    float bias[4];
#pragma unroll
    for (int jj = 0; jj < 4; jj++) bias[jj] = bb[(size_t)layer * Dm + j0 + jj * 16 + tx];
#pragma unroll
    for (int ii = 0; ii < 8; ii++) {
        size_t row = (size_t)(m0 + ii * 16 + ty);
#pragma unroll
        for (int jj = 0; jj < 4; jj++)
            g_zx[row * 4096 + n0 + jj * 16 + tx] = hsum2(acc[ii][jj]) + bias[jj];
    }
}

// ---------------- kernel 3: sequential scan ----------------------------------
// 128 CTAs x 256 threads, persistent. CTA b owns dims 8b..8b+7, warp w -> dim.
// Lane = blk*8 + chunk: blk picks gate matrix, chunk picks 128-wide k range.
// Arrival: per-warp smem atom (acq_rel); 8th warp fires one global red.release.
// Wait: warp0 lane0 polls L2 counter; fans out via smem release flag.
// Exactly one __syncthreads per step (after staging).
__global__ __launch_bounds__(256, 1) void scan_kernel(
    const float* __restrict__ Wf1, const float* __restrict__ Wf2,
    const float* __restrict__ Wta, const float* __restrict__ Wtb,
    const float* __restrict__ dt_ptr, int layer)
{
    __shared__ __align__(16) float sh[2][Dm];   // double-buffered h stage
    __shared__ unsigned s_flag;                  // last step released to CTA
    __shared__ unsigned s_acnt;                  // per-CTA warp arrivals (monotonic)

    const int tid  = threadIdx.x;
    const int lane = tid & 31;
    const int w    = tid >> 5;               // warp -> dim
    const int blk  = lane >> 3;              // gate 0..3
    const int ch   = lane & 7;               // k chunk
    const int dim  = blockIdx.x * 8 + w;
    const float dt = dt_ptr[0];
    const unsigned base = (unsigned)layer * 2047u * 128u;
    unsigned* const cnt = &g_bar_count;

    const unsigned flag_a = (unsigned)__cvta_generic_to_shared(&s_flag);
    const unsigned acnt_a = (unsigned)__cvta_generic_to_shared(&s_acnt);

    if (tid == 0) { s_flag = 0u; s_acnt = 0u; }

    const float* Wsel = (blk == 0) ? Wf1 : ((blk == 1) ? Wf2 : ((blk == 2) ? Wta : Wtb));
    const float* Wp = Wsel + (size_t)layer * 2 * Dm * Dm
                    + (size_t)(Dm + ch * 128) * Dm + dim;

    // this lane's 128 Wh values as 64 f32x2 pairs
    u64 wreg[64];
#pragma unroll
    for (int i = 0; i < 64; i++)
        wreg[i] = pack2(Wp[(size_t)(2 * i) * Dm], Wp[(size_t)(2 * i + 1) * Dm]);

    float* __restrict__ outseq = g_seq[(layer + 1) & 1];
    const bool zlane = (ch == 0);
    float zx_cur = zlane ? __ldg(&g_zx[(size_t)blk * Dm + dim]) : 0.0f;

    // staging indices (fixed per thread): handles h[sc*128 + sf*4 .. +3]
    const int sc = tid & 7, sf = tid >> 3;
    const float* const myh0 = &g_h[0][sc * 128 + sf * 4];
    const float* const myh1 = &g_h[1][sc * 128 + sf * 4];
    float* const mysh0 = &sh[0][sf * 32 + sc * 4];
    float* const mysh1 = &sh[1][sf * 32 + sc * 4];

    __syncthreads();   // covers s_flag/s_acnt init

    for (int t = 0; t < Tm; ++t) {
        // prefetch Zx for next step early (DRAM latency hides under the spin)
        float zx_next = (zlane && t + 1 < Tm)
            ? __ldg(&g_zx[(size_t)(t + 1) * 4096 + blk * Dm + dim]) : 0.0f;

        if (t > 0) {
            // warp0 lane0 polls the global counter; others spin cheaply on smem
            if (w == 0 && lane == 0) {
                const unsigned target = base + 128u * (unsigned)t;
                unsigned v;
                do {
                    asm volatile("ld.acquire.gpu.global.u32 %0, [%1];"
                                 : "=r"(v) : "l"(cnt) : "memory");
                } while ((int)(v - target) < 0);
                asm volatile("st.release.cta.shared.u32 [%0], %1;"
                             :: "r"(flag_a), "r"((unsigned)t) : "memory");
            }
            unsigned f;
            do {
                asm volatile("ld.acquire.cta.shared.u32 %0, [%1];"
                             : "=r"(f) : "r"(flag_a) : "memory");
            } while ((int)(f - (unsigned)t) < 0);
        }

        // ---- stage h_t into smem (chunk-interleaved, conflict-free) ----
        float* mysh = (t & 1) ? mysh1 : mysh0;
        if (t == 0) {
            mysh[0] = 0.0f; mysh[1] = 0.0f; mysh[2] = 0.0f; mysh[3] = 0.0f;
        } else {
            float4 v = __ldcg((const float4*)((t & 1) ? myh1 : myh0));
            mysh[0] = v.x; mysh[1] = v.y; mysh[2] = v.z; mysh[3] = v.w;
        }
        __syncthreads();

        // ---- partial dot: 128 k via 64 packed FMAs, 4 accumulator chains ----
        u64 a0 = 0ull, a1 = 0ull, a2 = 0ull, a3 = 0ull;
        const float4* sh4 = (const float4*)sh[t & 1];
#pragma unroll
        for (int f = 0; f < 32; f += 2) {
            float4 h0 = sh4[f * 8 + ch];
            float4 h1 = sh4[(f + 1) * 8 + ch];
            a0 = ffma2(pack2(h0.x, h0.y), wreg[2 * f + 0], a0);
            a1 = ffma2(pack2(h0.z, h0.w), wreg[2 * f + 1], a1);
            a2 = ffma2(pack2(h1.x, h1.y), wreg[2 * f + 2], a2);
            a3 = ffma2(pack2(h1.z, h1.w), wreg[2 * f + 3], a3);
        }
        float s = hsum2(fadd2(fadd2(a0, a1), fadd2(a2, a3)));
        s += __shfl_xor_sync(0xffffffffu, s, 1);
        s += __shfl_xor_sync(0xffffffffu, s, 2);
        s += __shfl_xor_sync(0xffffffffu, s, 4);
        if (zlane) s += zx_cur;

        float z1 = __shfl_sync(0xffffffffu, s, 0);
        float z2 = __shfl_sync(0xffffffffu, s, 8);
        float za = __shfl_sync(0xffffffffu, s, 16);
        float zb = __shfl_sync(0xffffffffu, s, 24);

        float f1 = fast_tanh(z1);
        float f2 = fast_tanh(z2);
        float g  = fast_sigmoid(zb - za * dt);   // sigmoid(-za*dt+zb)
        float hn = g * f1 + (1.0f - g) * f2;

        if (lane == 0) {
            if (t + 1 < Tm) {
                // publish h(t+1): 4B store, then hierarchical arrival
                asm volatile("st.relaxed.gpu.global.f32 [%0], %1;"
                             :: "l"(&g_h[(t + 1) & 1][dim]), "f"(hn) : "memory");
                unsigned old;
                asm volatile("atom.acq_rel.cta.shared.add.u32 %0, [%1], %2;"
                             : "=r"(old) : "r"(acnt_a), "r"(1u) : "memory");
                if (old == 8u * (unsigned)t + 7u)    // 8th warp of this step
                    asm volatile("red.release.gpu.global.add.u32 [%0], %1;"
                                 :: "l"(cnt), "r"(1u) : "memory");
            }
            // DRAM-bound seq store AFTER the release (off the fence drain path)
            outseq[(size_t)t * Dm + dim] = hn;
        }
        zx_cur = zx_next;
        // no trailing sync: double-buffered sh + per-step sync bounds skew
    }
}

// ---------------- kernel 4: emit final h -------------------------------------
__global__ void copy_out_kernel(float* __restrict__ out) {
    out[threadIdx.x] = g_seq[0][(size_t)(Tm - 1) * Dm + threadIdx.x];
}

// ---------------- launch ------------------------------------------------------
extern "C" void kernel_launch(void* const* d_in, const int* in_sizes, int n_in,
                              void* d_out, int out_size) {
    const float* x    = (const float*)d_in[0];
    const float* rn   = (const float*)d_in[1];
    const float* dtp  = (const float*)d_in[2];
    const float* rw   = (const float*)d_in[3];
    const float* rb   = (const float*)d_in[4];
    const float* Wf1  = (const float*)d_in[5];
    const float* bf1  = (const float*)d_in[6];
    const float* Wf2  = (const float*)d_in[7];
    const float* bf2  = (const float*)d_in[8];
    const float* Wta  = (const float*)d_in[9];
    const float* bta  = (const float*)d_in[10];
    const float* Wtb  = (const float*)d_in[11];
    const float* btb  = (const float*)d_in[12];

    bias_kernel<<<(Tm * Dm) / 256, 256>>>(x, rn, rw, rb);

    for (int l = 0; l < Lm; ++l) {
        dim3 grid(4 * Dm / 64, Tm / 128);
        gemm_zx<<<grid, 256>>>(Wf1, Wf2, Wta, Wtb, bf1, bf2, bta, btb, l);
        scan_kernel<<<128, 256>>>(Wf1, Wf2, Wta, Wtb, dtp, l);
    }

    copy_out_kernel<<<1, Dm>>>((float*)d_out);
}